// round 1
// baseline (speedup 1.0000x reference)
#include <cuda_runtime.h>
#include <cstdint>

// Problem constants
#define Bb 64
#define Cc 64
#define Tt 128
#define Vv 25
#define Rr 8
#define TSs 9
#define OUTo 64

// Scratch (device globals — no allocation allowed)
__device__ float g_xbar[Bb * Cc * Vv];          // (b,c,v) mean over t
__device__ float g_rel[Bb * Rr * Vv * Vv];      // (b,r,i,j)
__device__ float g_z[Bb * Cc * Tt * Vv];        // (b,c,t,v) intermediate

// ---------- packed f32x2 helpers (sm_103a FFMA2 path) ----------
__device__ __forceinline__ void ffma2(unsigned long long& acc,
                                      unsigned long long a,
                                      unsigned long long b) {
    asm("fma.rn.f32x2 %0, %1, %2, %0;" : "+l"(acc) : "l"(a), "l"(b));
}
__device__ __forceinline__ unsigned long long splat2(float x) {
    unsigned long long r;
    unsigned int xu = __float_as_uint(x);
    asm("mov.b64 %0, {%1, %1};" : "=l"(r) : "r"(xu));
    return r;
}

// ============================================================
// K1: xbar[b,c,v] = mean_t x[b,c,t,v].  grid = B*C, block = 128
// ============================================================
__global__ void k1_xbar(const float* __restrict__ x) {
    __shared__ float xs[Tt * Vv];      // 3200
    __shared__ float part[5][Vv];
    int bc = blockIdx.x, tid = threadIdx.x;
    const float* xg = x + (size_t)bc * (Tt * Vv);
    for (int idx = tid; idx < Tt * Vv; idx += 128) xs[idx] = xg[idx];
    __syncthreads();
    if (tid < 125) {
        int v = tid % 25, s = tid / 25;
        int t0 = s * 26;
        int t1 = t0 + 26; if (t1 > Tt) t1 = Tt;
        float acc = 0.f;
        for (int t = t0; t < t1; t++) acc += xs[t * Vv + v];
        part[s][v] = acc;
    }
    __syncthreads();
    if (tid < Vv) {
        float acc = part[0][tid] + part[1][tid] + part[2][tid] + part[3][tid] + part[4][tid];
        g_xbar[bc * Vv + tid] = acc * (1.f / (float)Tt);
    }
}

// ============================================================
// K2: rel[b,r,i,j] = tanh(x1[b,r,i] - x2[b,r,j]).  grid = B, block = 256
// ============================================================
__global__ void k2_rel(const float* __restrict__ W1, const float* __restrict__ b1,
                       const float* __restrict__ W2, const float* __restrict__ b2) {
    __shared__ float xb[Cc * Vv];      // 1600
    __shared__ float w1s[Rr * Cc], w2s[Rr * Cc];
    __shared__ float x1s[Rr * Vv], x2s[Rr * Vv];
    __shared__ float b1s[Rr], b2s[Rr];
    int b = blockIdx.x, tid = threadIdx.x;
    for (int idx = tid; idx < Cc * Vv; idx += 256) xb[idx] = g_xbar[b * (Cc * Vv) + idx];
    for (int idx = tid; idx < Rr * Cc; idx += 256) { w1s[idx] = W1[idx]; w2s[idx] = W2[idx]; }
    if (tid < Rr) { b1s[tid] = b1[tid]; b2s[tid] = b2[tid]; }
    __syncthreads();
    if (tid < Rr * Vv) {
        int r = tid / Vv, v = tid % Vv;
        float a1 = b1s[r], a2 = b2s[r];
        #pragma unroll 8
        for (int c = 0; c < Cc; c++) {
            float xv = xb[c * Vv + v];
            a1 = fmaf(w1s[r * Cc + c], xv, a1);
            a2 = fmaf(w2s[r * Cc + c], xv, a2);
        }
        x1s[tid] = a1; x2s[tid] = a2;
    }
    __syncthreads();
    for (int idx = tid; idx < Rr * Vv * Vv; idx += 256) {
        int r = idx / (Vv * Vv), rem = idx % (Vv * Vv);
        int i = rem / Vv, j = rem % Vv;
        g_rel[b * (Rr * Vv * Vv) + idx] = tanhf(x1s[r * Vv + i] - x2s[r * Vv + j]);
    }
}

// ============================================================
// K3: per (b,c) block:
//   Adyn_k[v][i] = sum_r W4[(c*9+k),r]*rel[b,r,v,i] + b4[c*9+k] + A[v,i]
//   z[t][i]      = sum_{k,v} xpad[t+k][v] * Adyn_k[v][i]
// grid = B*C, block = 128, dyn smem = 48024 B
// ============================================================
#define IPAD 28                     // i padded 25 -> 28 for vec4 f32x2 loads
#define AKP_SZ (TSs * Vv * IPAD)    // 6300
#define XS_SZ ((Tt + TSs - 1) * Vv) // 3400

__global__ __launch_bounds__(128) void k3_z(const float* __restrict__ x,
                                            const float* __restrict__ A,
                                            const float* __restrict__ W4,
                                            const float* __restrict__ b4) {
    extern __shared__ __align__(16) float sm[];
    float* Akp   = sm;                  // [9][25][28] = 6300
    float* rel_s = sm + AKP_SZ;         // 5000 (phase 1)
    float* a_s   = rel_s + Rr * Vv * Vv;// 625
    float* w4s   = a_s + Vv * Vv;       // 72
    float* b4s   = w4s + TSs * Rr;      // 9
    float* xs    = sm + AKP_SZ;         // 3400 (phase 2, aliases rel_s)

    int bc = blockIdx.x;
    int b = bc >> 6, c = bc & 63;
    int tid = threadIdx.x;

    // ---- phase 1 loads ----
    const float* relg = g_rel + b * (Rr * Vv * Vv);
    for (int idx = tid; idx < Rr * Vv * Vv; idx += 128) rel_s[idx] = relg[idx];
    for (int idx = tid; idx < Vv * Vv; idx += 128) a_s[idx] = A[idx];
    if (tid < TSs * Rr) w4s[tid] = W4[c * (TSs * Rr) + tid];
    if (tid < TSs) b4s[tid] = b4[c * TSs + tid];
    __syncthreads();

    // ---- build Adyn (padded) ----
    for (int vi = tid; vi < Vv * Vv; vi += 128) {
        float r8[Rr];
        #pragma unroll
        for (int r = 0; r < Rr; r++) r8[r] = rel_s[r * (Vv * Vv) + vi];
        float av = a_s[vi];
        int v = vi / Vv, i = vi % Vv;
        #pragma unroll
        for (int k = 0; k < TSs; k++) {
            float acc = b4s[k] + av;
            #pragma unroll
            for (int r = 0; r < Rr; r++) acc = fmaf(w4s[k * Rr + r], r8[r], acc);
            Akp[(k * Vv + v) * IPAD + i] = acc;
        }
    }
    // zero the i=25..27 padding
    for (int idx = tid; idx < TSs * Vv * 3; idx += 128) {
        int kv = idx / 3, j = idx % 3;
        Akp[kv * IPAD + Vv + j] = 0.f;
    }
    __syncthreads();   // rel_s no longer needed; Akp complete

    // ---- phase 2: causal-padded x tile ----
    const float* xg = x + (size_t)bc * (Tt * Vv);
    for (int idx = tid; idx < XS_SZ; idx += 128)
        xs[idx] = (idx >= (TSs - 1) * Vv) ? xg[idx - (TSs - 1) * Vv] : 0.f;
    __syncthreads();

    // ---- z compute: thread owns t = tid (128 threads) ----
    unsigned long long zacc[IPAD / 2];
    #pragma unroll
    for (int p = 0; p < IPAD / 2; p++) zacc[p] = 0ull;
    int t = tid;
    #pragma unroll 1
    for (int v = 0; v < Vv; v++) {
        float xv[TSs];
        #pragma unroll
        for (int k = 0; k < TSs; k++) xv[k] = xs[(t + k) * Vv + v];
        #pragma unroll
        for (int k = 0; k < TSs; k++) {
            unsigned long long xsp = splat2(xv[k]);
            const ulonglong2* ap =
                reinterpret_cast<const ulonglong2*>(&Akp[(k * Vv + v) * IPAD]);
            #pragma unroll
            for (int q = 0; q < 7; q++) {
                ulonglong2 a2 = ap[q];        // LDS.128, warp-uniform broadcast
                ffma2(zacc[2 * q],     a2.x, xsp);
                ffma2(zacc[2 * q + 1], a2.y, xsp);
            }
        }
    }

    // ---- stage z in smem (reuse xs) for coalesced global store ----
    __syncthreads();   // all threads done reading xs
    float* zstage = xs;                 // 3200 used
    #pragma unroll
    for (int p = 0; p < IPAD / 2; p++) {
        float2 f = *reinterpret_cast<float2*>(&zacc[p]);
        int i0 = 2 * p;
        if (i0 < Vv)     zstage[t * Vv + i0] = f.x;
        if (i0 + 1 < Vv) zstage[t * Vv + i0 + 1] = f.y;
    }
    __syncthreads();
    float* zg = g_z + (size_t)bc * (Tt * Vv);
    for (int idx = tid; idx < Tt * Vv; idx += 128) zg[idx] = zstage[idx];
}

// ============================================================
// K4: out[b,o,n] = b3[o] + sum_c W3[o,c] * z[b,c,n],  n = t*25+v in [0,3200)
// grid = (50 n-tiles of 64, B), block = 128 (2 o-halves x 64 n)
// ============================================================
__global__ __launch_bounds__(128) void k4_conv3(const float* __restrict__ W3,
                                                const float* __restrict__ b3,
                                                float* __restrict__ out) {
    __shared__ __align__(16) float w3t[Cc * OUTo];  // [c][o]
    __shared__ float zs[Cc * 64];                   // [c][n]
    __shared__ float b3s[OUTo];
    int nt = blockIdx.x, b = blockIdx.y;
    int tid = threadIdx.x;

    for (int idx = tid; idx < OUTo * Cc; idx += 128) {
        int o = idx >> 6, c = idx & 63;
        w3t[c * OUTo + o] = W3[idx];
    }
    if (tid < OUTo) b3s[tid] = b3[tid];
    const float* zg = g_z + (size_t)b * (Cc * Tt * Vv) + nt * 64;
    for (int idx = tid; idx < Cc * 64; idx += 128) {
        int c = idx >> 6, j = idx & 63;
        zs[idx] = zg[(size_t)c * (Tt * Vv) + j];
    }
    __syncthreads();

    int n = tid & 63, oh = tid >> 6;
    int o0 = oh * 32;
    unsigned long long acc[16];
    #pragma unroll
    for (int q = 0; q < 16; q++) acc[q] = 0ull;

    #pragma unroll 4
    for (int c = 0; c < Cc; c++) {
        unsigned long long zsp = splat2(zs[c * 64 + n]);
        const ulonglong2* wp =
            reinterpret_cast<const ulonglong2*>(&w3t[c * OUTo + o0]);
        #pragma unroll
        for (int q = 0; q < 8; q++) {
            ulonglong2 w2 = wp[q];
            ffma2(acc[2 * q],     w2.x, zsp);
            ffma2(acc[2 * q + 1], w2.y, zsp);
        }
    }

    float* og = out + (size_t)(b * OUTo) * (Tt * Vv) + nt * 64 + n;
    #pragma unroll
    for (int q = 0; q < 16; q++) {
        float2 f = *reinterpret_cast<float2*>(&acc[q]);
        int oa = o0 + 2 * q, ob = oa + 1;
        og[(size_t)oa * (Tt * Vv)] = f.x + b3s[oa];
        og[(size_t)ob * (Tt * Vv)] = f.y + b3s[ob];
    }
}

// ============================================================
extern "C" void kernel_launch(void* const* d_in, const int* in_sizes, int n_in,
                              void* d_out, int out_size) {
    const float* x  = (const float*)d_in[0];
    const float* A  = (const float*)d_in[1];
    const float* W1 = (const float*)d_in[2];
    const float* b1 = (const float*)d_in[3];
    const float* W2 = (const float*)d_in[4];
    const float* b2 = (const float*)d_in[5];
    const float* W4 = (const float*)d_in[6];
    const float* b4 = (const float*)d_in[7];
    const float* W3 = (const float*)d_in[8];
    const float* b3 = (const float*)d_in[9];
    float* out = (float*)d_out;

    k1_xbar<<<Bb * Cc, 128>>>(x);
    k2_rel<<<Bb, 256>>>(W1, b1, W2, b2);
    k3_z<<<Bb * Cc, 128, (AKP_SZ + 5706) * sizeof(float)>>>(x, A, W4, b4);
    k4_conv3<<<dim3(50, Bb), 128>>>(W3, b3, out);
}

// round 3
// speedup vs baseline: 1.0902x; 1.0902x over previous
#include <cuda_runtime.h>
#include <cstdint>

// Problem constants
#define Bb 64
#define Cc 64
#define Tt 128
#define Vv 25
#define Rr 8
#define TSs 9
#define OUTo 64

// Scratch (device globals — no allocation allowed)
__device__ float g_xbar[Bb * Cc * Vv];          // (b,c,v) mean over t
__device__ float g_rel[Bb * Rr * Vv * Vv];      // (b,r,i,j)
__device__ float g_z[Bb * Cc * Tt * Vv];        // (b,c,t,v) intermediate

// ---------- packed f32x2 helpers (sm_103a FFMA2 path) ----------
__device__ __forceinline__ void ffma2(unsigned long long& acc,
                                      unsigned long long a,
                                      unsigned long long b) {
    asm("fma.rn.f32x2 %0, %1, %2, %0;" : "+l"(acc) : "l"(a), "l"(b));
}
__device__ __forceinline__ unsigned long long splat2(float x) {
    unsigned long long r;
    unsigned int xu = __float_as_uint(x);
    asm("mov.b64 %0, {%1, %1};" : "=l"(r) : "r"(xu));
    return r;
}

// ============================================================
// K1: xbar[b,c,v] = mean_t x[b,c,t,v].  grid = B*C, block = 128
// ============================================================
__global__ void k1_xbar(const float* __restrict__ x) {
    __shared__ float xs[Tt * Vv];      // 3200
    __shared__ float part[5][Vv];
    int bc = blockIdx.x, tid = threadIdx.x;
    const float* xg = x + (size_t)bc * (Tt * Vv);
    for (int idx = tid; idx < Tt * Vv; idx += 128) xs[idx] = xg[idx];
    __syncthreads();
    if (tid < 125) {
        int v = tid % 25, s = tid / 25;
        int t0 = s * 26;
        int t1 = t0 + 26; if (t1 > Tt) t1 = Tt;
        float acc = 0.f;
        for (int t = t0; t < t1; t++) acc += xs[t * Vv + v];
        part[s][v] = acc;
    }
    __syncthreads();
    if (tid < Vv) {
        float acc = part[0][tid] + part[1][tid] + part[2][tid] + part[3][tid] + part[4][tid];
        g_xbar[bc * Vv + tid] = acc * (1.f / (float)Tt);
    }
}

// ============================================================
// K2: rel[b,r,i,j] = tanh(x1[b,r,i] - x2[b,r,j]).  grid = B, block = 256
// ============================================================
__global__ void k2_rel(const float* __restrict__ W1, const float* __restrict__ b1,
                       const float* __restrict__ W2, const float* __restrict__ b2) {
    __shared__ float xb[Cc * Vv];      // 1600
    __shared__ float w1s[Rr * Cc], w2s[Rr * Cc];
    __shared__ float x1s[Rr * Vv], x2s[Rr * Vv];
    __shared__ float b1s[Rr], b2s[Rr];
    int b = blockIdx.x, tid = threadIdx.x;
    for (int idx = tid; idx < Cc * Vv; idx += 256) xb[idx] = g_xbar[b * (Cc * Vv) + idx];
    for (int idx = tid; idx < Rr * Cc; idx += 256) { w1s[idx] = W1[idx]; w2s[idx] = W2[idx]; }
    if (tid < Rr) { b1s[tid] = b1[tid]; b2s[tid] = b2[tid]; }
    __syncthreads();
    if (tid < Rr * Vv) {
        int r = tid / Vv, v = tid % Vv;
        float a1 = b1s[r], a2 = b2s[r];
        #pragma unroll 8
        for (int c = 0; c < Cc; c++) {
            float xv = xb[c * Vv + v];
            a1 = fmaf(w1s[r * Cc + c], xv, a1);
            a2 = fmaf(w2s[r * Cc + c], xv, a2);
        }
        x1s[tid] = a1; x2s[tid] = a2;
    }
    __syncthreads();
    for (int idx = tid; idx < Rr * Vv * Vv; idx += 256) {
        int r = idx / (Vv * Vv), rem = idx % (Vv * Vv);
        int i = rem / Vv, j = rem % Vv;
        g_rel[b * (Rr * Vv * Vv) + idx] = tanhf(x1s[r * Vv + i] - x2s[r * Vv + j]);
    }
}

// ============================================================
// K3: per (b,c) block:
//   Adyn_k[v][i] = sum_r W4[(c*9+k),r]*rel[b,r,v,i] + b4[c*9+k] + A[v,i]
//   z[t][i]      = sum_{k,v} xpad[t+k][v] * Adyn_k[v][i]
// grid = B*C, block = 64 (each thread owns t-pair 2*tid, 2*tid+1)
// dyn smem = 48024 B
// ============================================================
#define IPAD 28                     // i padded 25 -> 28 for LDS.128 of f32x2 pairs
#define AKP_SZ (TSs * Vv * IPAD)    // 6300
#define RL 138                      // padded x row length in [v][t] layout (even)
#define XS_SZ (Vv * RL)             // 3450

__global__ __launch_bounds__(64) void k3_z(const float* __restrict__ x,
                                           const float* __restrict__ A,
                                           const float* __restrict__ W4,
                                           const float* __restrict__ b4) {
    extern __shared__ __align__(16) float sm[];
    float* Akp   = sm;                  // [9][25][28] = 6300
    float* rel_s = sm + AKP_SZ;         // 5000 (phase 1)
    float* a_s   = rel_s + Rr * Vv * Vv;// 625
    float* w4s   = a_s + Vv * Vv;       // 72
    float* b4s   = w4s + TSs * Rr;      // 9
    float* xs    = sm + AKP_SZ;         // [v][RL] 3450 (phase 2, aliases rel_s)

    int bc = blockIdx.x;
    int b = bc >> 6, c = bc & 63;
    int tid = threadIdx.x;

    // ---- phase 1 loads ----
    const float* relg = g_rel + b * (Rr * Vv * Vv);
    for (int idx = tid; idx < Rr * Vv * Vv; idx += 64) rel_s[idx] = relg[idx];
    for (int idx = tid; idx < Vv * Vv; idx += 64) a_s[idx] = A[idx];
    // FIX (round-2 bug): 72 > blockDim 64 — must be a strided loop, not a
    // single predicated store, or taps k=7..8 get garbage coefficients.
    for (int idx = tid; idx < TSs * Rr; idx += 64) w4s[idx] = W4[c * (TSs * Rr) + idx];
    if (tid < TSs) b4s[tid] = b4[c * TSs + tid];
    __syncthreads();

    // ---- build Adyn (padded over i) ----
    for (int vi = tid; vi < Vv * Vv; vi += 64) {
        float r8[Rr];
        #pragma unroll
        for (int r = 0; r < Rr; r++) r8[r] = rel_s[r * (Vv * Vv) + vi];
        float av = a_s[vi];
        int v = vi / Vv, i = vi % Vv;
        #pragma unroll
        for (int k = 0; k < TSs; k++) {
            float acc = b4s[k] + av;
            #pragma unroll
            for (int r = 0; r < Rr; r++) acc = fmaf(w4s[k * Rr + r], r8[r], acc);
            Akp[(k * Vv + v) * IPAD + i] = acc;
        }
    }
    // zero the i=25..27 padding
    for (int idx = tid; idx < TSs * Vv * 3; idx += 64) {
        int kv = idx / 3, j = idx % 3;
        Akp[kv * IPAD + Vv + j] = 0.f;
    }
    __syncthreads();   // rel_s dead; Akp complete

    // ---- phase 2: causal-padded x tile, transposed to [v][t] ----
    const float* xg = x + (size_t)bc * (Tt * Vv);
    for (int idx = tid; idx < XS_SZ; idx += 64) {
        int v = idx / RL, t = idx - v * RL;
        float val = 0.f;
        if (t >= (TSs - 1) && t < Tt + TSs - 1) val = xg[(t - (TSs - 1)) * Vv + v];
        xs[idx] = val;
    }
    __syncthreads();

    // ---- z compute: thread owns t-pair (t2, t2+1) ----
    int t2 = tid * 2;
    unsigned long long acc0[IPAD / 2], acc1[IPAD / 2];
    #pragma unroll
    for (int p = 0; p < IPAD / 2; p++) { acc0[p] = 0ull; acc1[p] = 0ull; }

    #pragma unroll 1
    for (int v = 0; v < Vv; v++) {
        // 10 taps covering both t's: xs[v][t2 + 0..9], loaded as 5 LDS.64
        float xv[TSs + 1];
        const float2* xrow = reinterpret_cast<const float2*>(&xs[v * RL + t2]);
        #pragma unroll
        for (int j = 0; j < 5; j++) {
            float2 p2 = xrow[j];
            xv[2 * j] = p2.x; xv[2 * j + 1] = p2.y;
        }
        #pragma unroll
        for (int k = 0; k < TSs; k++) {
            unsigned long long s0 = splat2(xv[k]);       // tap for t2
            unsigned long long s1 = splat2(xv[k + 1]);   // tap for t2+1
            const ulonglong2* ap =
                reinterpret_cast<const ulonglong2*>(&Akp[(k * Vv + v) * IPAD]);
            #pragma unroll
            for (int q = 0; q < 7; q++) {
                ulonglong2 a2 = ap[q];      // warp-uniform broadcast LDS.128
                ffma2(acc0[2 * q],     a2.x, s0);
                ffma2(acc0[2 * q + 1], a2.y, s0);
                ffma2(acc1[2 * q],     a2.x, s1);
                ffma2(acc1[2 * q + 1], a2.y, s1);
            }
        }
    }

    // ---- stage z in smem (reuse xs) for coalesced global store ----
    __syncthreads();
    float* zstage = xs;                 // 3200 floats used
    #pragma unroll
    for (int p = 0; p < IPAD / 2; p++) {
        float2 f0 = *reinterpret_cast<float2*>(&acc0[p]);
        float2 f1 = *reinterpret_cast<float2*>(&acc1[p]);
        int i0 = 2 * p;
        if (i0 < Vv)     { zstage[t2 * Vv + i0]           = f0.x;
                           zstage[(t2 + 1) * Vv + i0]     = f1.x; }
        if (i0 + 1 < Vv) { zstage[t2 * Vv + i0 + 1]       = f0.y;
                           zstage[(t2 + 1) * Vv + i0 + 1] = f1.y; }
    }
    __syncthreads();
    float* zg = g_z + (size_t)bc * (Tt * Vv);
    for (int idx = tid; idx < Tt * Vv; idx += 64) zg[idx] = zstage[idx];
}

// ============================================================
// K4: out[b,o,n] = b3[o] + sum_c W3[o,c] * z[b,c,n],  n in [0,3200)
// grid = (50 n-tiles of 64, B), block = 128
// Each thread: 8 consecutive o (packed as 4 f32x2 o-pairs) x 4 n.
// Per c-step: 2 LDS.128 (w) + 1 LDS.128 (z) + 4 splats + 16 FFMA2.
// ============================================================
__global__ __launch_bounds__(128) void k4_conv3(const float* __restrict__ W3,
                                                const float* __restrict__ b3,
                                                float* __restrict__ out) {
    __shared__ __align__(16) float w3t[Cc * OUTo];  // [c][o] 16KB
    __shared__ __align__(16) float zs[Cc * 64];     // [c][n] 16KB
    __shared__ float b3s[OUTo];
    int nt = blockIdx.x, b = blockIdx.y;
    int tid = threadIdx.x;

    for (int idx = tid; idx < OUTo * Cc; idx += 128) {
        int o = idx >> 6, c = idx & 63;
        w3t[c * OUTo + o] = W3[idx];
    }
    if (tid < OUTo) b3s[tid] = b3[tid];
    const float* zg = g_z + (size_t)b * (Cc * Tt * Vv) + nt * 64;
    for (int idx = tid; idx < Cc * 64; idx += 128) {
        int c = idx >> 6, j = idx & 63;
        zs[idx] = zg[(size_t)c * (Tt * Vv) + j];
    }
    __syncthreads();

    int og = tid & 7;          // 8 o-groups
    int ng = tid >> 3;         // 16 n-groups
    int o0 = og * 8, n0 = ng * 4;

    unsigned long long acc[4][4];   // [o-pair][n]
    #pragma unroll
    for (int p = 0; p < 4; p++)
        #pragma unroll
        for (int q = 0; q < 4; q++) acc[p][q] = 0ull;

    #pragma unroll 4
    for (int c = 0; c < Cc; c++) {
        const ulonglong2* wp =
            reinterpret_cast<const ulonglong2*>(&w3t[c * OUTo + o0]);
        ulonglong2 wa = wp[0];   // o-pairs (o0,o0+1),(o0+2,o0+3)
        ulonglong2 wb = wp[1];   // (o0+4,o0+5),(o0+6,o0+7)
        float4 z4 = *reinterpret_cast<const float4*>(&zs[c * 64 + n0]);
        unsigned long long zs0 = splat2(z4.x), zs1 = splat2(z4.y);
        unsigned long long zs2 = splat2(z4.z), zs3 = splat2(z4.w);
        ffma2(acc[0][0], wa.x, zs0); ffma2(acc[0][1], wa.x, zs1);
        ffma2(acc[0][2], wa.x, zs2); ffma2(acc[0][3], wa.x, zs3);
        ffma2(acc[1][0], wa.y, zs0); ffma2(acc[1][1], wa.y, zs1);
        ffma2(acc[1][2], wa.y, zs2); ffma2(acc[1][3], wa.y, zs3);
        ffma2(acc[2][0], wb.x, zs0); ffma2(acc[2][1], wb.x, zs1);
        ffma2(acc[2][2], wb.x, zs2); ffma2(acc[2][3], wb.x, zs3);
        ffma2(acc[3][0], wb.y, zs0); ffma2(acc[3][1], wb.y, zs1);
        ffma2(acc[3][2], wb.y, zs2); ffma2(acc[3][3], wb.y, zs3);
    }

    size_t obase = (size_t)b * OUTo * (Tt * Vv) + nt * 64 + n0;
    #pragma unroll
    for (int p = 0; p < 4; p++) {
        int oA = o0 + 2 * p, oB = oA + 1;
        float bA = b3s[oA], bB = b3s[oB];
        float* pA = out + obase + (size_t)oA * (Tt * Vv);
        float* pB = out + obase + (size_t)oB * (Tt * Vv);
        #pragma unroll
        for (int q = 0; q < 4; q++) {
            float2 f = *reinterpret_cast<float2*>(&acc[p][q]);
            pA[q] = f.x + bA;
            pB[q] = f.y + bB;
        }
    }
}

// ============================================================
extern "C" void kernel_launch(void* const* d_in, const int* in_sizes, int n_in,
                              void* d_out, int out_size) {
    const float* x  = (const float*)d_in[0];
    const float* A  = (const float*)d_in[1];
    const float* W1 = (const float*)d_in[2];
    const float* b1 = (const float*)d_in[3];
    const float* W2 = (const float*)d_in[4];
    const float* b2 = (const float*)d_in[5];
    const float* W4 = (const float*)d_in[6];
    const float* b4 = (const float*)d_in[7];
    const float* W3 = (const float*)d_in[8];
    const float* b3 = (const float*)d_in[9];
    float* out = (float*)d_out;

    k1_xbar<<<Bb * Cc, 128>>>(x);
    k2_rel<<<Bb, 256>>>(W1, b1, W2, b2);
    k3_z<<<Bb * Cc, 64, (AKP_SZ + 5706) * sizeof(float)>>>(x, A, W4, b4);
    k4_conv3<<<dim3(50, Bb), 128>>>(W3, b3, out);
}

// round 4
// speedup vs baseline: 1.6179x; 1.4840x over previous
#include <cuda_runtime.h>
#include <cstdint>

// Problem constants
#define Bb 64
#define Cc 64
#define Tt 128
#define Vv 25
#define Rr 8
#define TSs 9
#define OUTo 64

typedef unsigned long long ull;

// Scratch (device globals — no allocation allowed)
__device__ float g_xbar[Bb * Cc * Vv];          // (b,c,v) mean over t
__device__ float g_rel[Bb * Rr * Vv * Vv];      // (b,r,i,j)
__device__ float g_z[Bb * Cc * Tt * Vv];        // (b,c,t,v) intermediate

// ---------- packed f32x2 helpers (sm_103a FFMA2 path) ----------
__device__ __forceinline__ void ffma2(ull& acc, ull a, ull b) {
    asm("fma.rn.f32x2 %0, %1, %2, %0;" : "+l"(acc) : "l"(a), "l"(b));
}
__device__ __forceinline__ ull splat2(float x) {
    ull r;
    unsigned int xu = __float_as_uint(x);
    asm("mov.b64 %0, {%1, %1};" : "=l"(r) : "r"(xu));
    return r;
}
__device__ __forceinline__ float2 lo_hi(ull v) {
    float2 f;
    asm("mov.b64 {%0, %1}, %2;" : "=f"(f.x), "=f"(f.y) : "l"(v));
    return f;
}

// ============================================================
// K1: xbar[b,c,v] = mean_t x[b,c,t,v].  grid = B*C, block = 128
// ============================================================
__global__ void k1_xbar(const float* __restrict__ x) {
    __shared__ float xs[Tt * Vv];
    __shared__ float part[5][Vv];
    int bc = blockIdx.x, tid = threadIdx.x;
    const float* xg = x + (size_t)bc * (Tt * Vv);
    for (int idx = tid; idx < Tt * Vv; idx += 128) xs[idx] = xg[idx];
    __syncthreads();
    if (tid < 125) {
        int v = tid % 25, s = tid / 25;
        int t0 = s * 26;
        int t1 = t0 + 26; if (t1 > Tt) t1 = Tt;
        float acc = 0.f;
        for (int t = t0; t < t1; t++) acc += xs[t * Vv + v];
        part[s][v] = acc;
    }
    __syncthreads();
    if (tid < Vv) {
        float acc = part[0][tid] + part[1][tid] + part[2][tid] + part[3][tid] + part[4][tid];
        g_xbar[bc * Vv + tid] = acc * (1.f / (float)Tt);
    }
}

// ============================================================
// K2: rel[b,r,i,j] = tanh(x1[b,r,i] - x2[b,r,j]).  grid = B, block = 256
// ============================================================
__global__ void k2_rel(const float* __restrict__ W1, const float* __restrict__ b1,
                       const float* __restrict__ W2, const float* __restrict__ b2) {
    __shared__ float xb[Cc * Vv];
    __shared__ float w1s[Rr * Cc], w2s[Rr * Cc];
    __shared__ float x1s[Rr * Vv], x2s[Rr * Vv];
    __shared__ float b1s[Rr], b2s[Rr];
    int b = blockIdx.x, tid = threadIdx.x;
    for (int idx = tid; idx < Cc * Vv; idx += 256) xb[idx] = g_xbar[b * (Cc * Vv) + idx];
    for (int idx = tid; idx < Rr * Cc; idx += 256) { w1s[idx] = W1[idx]; w2s[idx] = W2[idx]; }
    if (tid < Rr) { b1s[tid] = b1[tid]; b2s[tid] = b2[tid]; }
    __syncthreads();
    if (tid < Rr * Vv) {
        int r = tid / Vv, v = tid % Vv;
        float a1 = b1s[r], a2 = b2s[r];
        #pragma unroll 8
        for (int c = 0; c < Cc; c++) {
            float xv = xb[c * Vv + v];
            a1 = fmaf(w1s[r * Cc + c], xv, a1);
            a2 = fmaf(w2s[r * Cc + c], xv, a2);
        }
        x1s[tid] = a1; x2s[tid] = a2;
    }
    __syncthreads();
    for (int idx = tid; idx < Rr * Vv * Vv; idx += 256) {
        int r = idx / (Vv * Vv), rem = idx % (Vv * Vv);
        int i = rem / Vv, j = rem % Vv;
        g_rel[b * (Rr * Vv * Vv) + idx] = tanhf(x1s[r * Vv + i] - x2s[r * Vv + j]);
    }
}

// ============================================================
// K3: per (b,c) block, 128 threads:
//   Adyn_k[v][i] = sum_r W4[(c*9+k),r]*rel[b,r,v,i] + b4[c*9+k] + A[v,i]
//   z[t][i]      = sum_{k,v} xpad[t+k][v] * Adyn_k[v][i]
// Thread layout: half = tid>>6 owns i-chunk (ulonglong2 q in [QB,QB+NQ));
//                tp = tid&63 owns t-pair (2*tp, 2*tp+1).
// Static smem: Akp 6300 + xs 3400 + w4s 72 + b4s 9 = 39,124 B -> 5 blocks/SM.
// ============================================================
#define IPAD 28                  // i padded 25 -> 28 (16B row stride multiple)
#define AKP_SZ (TSs * Vv * IPAD) // 6300
#define RL 136                   // x row length in [v][t] layout (8B aligned)
#define XS_SZ (Vv * RL)          // 3400

template <int NQ, int QB>
__device__ __forceinline__ void k3_compute(const float* __restrict__ Akp,
                                           const float* __restrict__ xs,
                                           int t2, ull* a0, ull* a1) {
    #pragma unroll
    for (int p = 0; p < 2 * NQ; p++) { a0[p] = 0ull; a1[p] = 0ull; }
    #pragma unroll 1
    for (int v = 0; v < Vv; v++) {
        float xv[TSs + 1];
        const float2* xr = reinterpret_cast<const float2*>(&xs[v * RL + t2]);
        #pragma unroll
        for (int j = 0; j < 5; j++) {
            float2 p2 = xr[j];
            xv[2 * j] = p2.x; xv[2 * j + 1] = p2.y;
        }
        #pragma unroll
        for (int k = 0; k < TSs; k++) {
            ull s0 = splat2(xv[k]);
            ull s1 = splat2(xv[k + 1]);
            const ulonglong2* ap =
                reinterpret_cast<const ulonglong2*>(&Akp[(k * Vv + v) * IPAD]) + QB;
            #pragma unroll
            for (int q = 0; q < NQ; q++) {
                ulonglong2 A2 = ap[q];     // warp-uniform broadcast
                ffma2(a0[2 * q],     A2.x, s0);
                ffma2(a0[2 * q + 1], A2.y, s0);
                ffma2(a1[2 * q],     A2.x, s1);
                ffma2(a1[2 * q + 1], A2.y, s1);
            }
        }
    }
}

__global__ __launch_bounds__(128) void k3_z(const float* __restrict__ x,
                                            const float* __restrict__ A,
                                            const float* __restrict__ W4,
                                            const float* __restrict__ b4) {
    __shared__ __align__(16) float Akp[AKP_SZ];
    __shared__ __align__(16) float xs[XS_SZ];
    __shared__ float w4s[TSs * Rr];
    __shared__ float b4s[TSs];

    int bc = blockIdx.x;
    int b = bc >> 6, c = bc & 63;
    int tid = threadIdx.x;

    if (tid < TSs * Rr) w4s[tid] = W4[c * (TSs * Rr) + tid];
    if (tid < TSs) b4s[tid] = b4[c * TSs + tid];
    __syncthreads();

    // ---- build Adyn directly from global rel/A (coalesced, L2-resident) ----
    const float* relg = g_rel + b * (Rr * Vv * Vv);
    for (int vi = tid; vi < Vv * Vv; vi += 128) {
        float r8[Rr];
        #pragma unroll
        for (int r = 0; r < Rr; r++) r8[r] = __ldg(&relg[r * (Vv * Vv) + vi]);
        float av = __ldg(&A[vi]);
        int v = vi / Vv, i = vi - v * Vv;
        #pragma unroll
        for (int k = 0; k < TSs; k++) {
            float acc = b4s[k] + av;
            #pragma unroll
            for (int r = 0; r < Rr; r++) acc = fmaf(w4s[k * Rr + r], r8[r], acc);
            Akp[(k * Vv + v) * IPAD + i] = acc;
        }
    }
    for (int idx = tid; idx < TSs * Vv * 3; idx += 128) {
        int kv = idx / 3, j = idx - kv * 3;
        Akp[kv * IPAD + Vv + j] = 0.f;
    }
    // ---- causal-padded x tile, transposed to [v][t] ----
    const float* xg = x + (size_t)bc * (Tt * Vv);
    for (int idx = tid; idx < XS_SZ; idx += 128) {
        int v = idx / RL, t = idx - v * RL;
        xs[idx] = (t >= (TSs - 1)) ? xg[(t - (TSs - 1)) * Vv + v] : 0.f;
    }
    __syncthreads();

    // ---- main compute ----
    int half = tid >> 6, tp = tid & 63, t2 = tp * 2;
    ull a0[8], a1[8];
    if (half == 0) k3_compute<4, 0>(Akp, xs, t2, a0, a1);
    else           k3_compute<3, 4>(Akp, xs, t2, a0, a1);
    __syncthreads();               // everyone done reading xs

    // ---- stage z (alias xs) for coalesced global store ----
    float* zst = xs;
    int qb = half * 4, nq = half ? 3 : 4;
    #pragma unroll
    for (int q = 0; q < 4; q++) {
        if (q < nq) {
            #pragma unroll
            for (int part = 0; part < 2; part++) {
                float2 f0 = lo_hi(a0[2 * q + part]);
                float2 f1 = lo_hi(a1[2 * q + part]);
                int i0 = (qb + q) * 4 + part * 2;
                if (i0 < Vv) {
                    zst[t2 * Vv + i0]       = f0.x;
                    zst[(t2 + 1) * Vv + i0] = f1.x;
                }
                if (i0 + 1 < Vv) {
                    zst[t2 * Vv + i0 + 1]       = f0.y;
                    zst[(t2 + 1) * Vv + i0 + 1] = f1.y;
                }
            }
        }
    }
    __syncthreads();
    float* zg = g_z + (size_t)bc * (Tt * Vv);
    for (int idx = tid; idx < Tt * Vv; idx += 128) zg[idx] = zst[idx];
}

// ============================================================
// K4: out[b,o,n] = b3[o] + sum_c W3[o,c] * z[b,c,n]
// grid = (25 n-tiles of 128, B), block = 256 (8 warps).
// o is WARP-UNIFORM (o0 = warp*8): both w LDS.128 are broadcasts.
// n0 = lane*4: z LDS.128 is one conflict-free coalesced access.
// Static smem: w3t 4096 + zs 8192 = 49,152 B (48KB).
// ============================================================
__global__ __launch_bounds__(256) void k4_conv3(const float* __restrict__ W3,
                                                const float* __restrict__ b3,
                                                float* __restrict__ out) {
    __shared__ __align__(16) float w3t[Cc * OUTo];  // [c][o] 16KB
    __shared__ __align__(16) float zs[Cc * 128];    // [c][n] 32KB
    int nt = blockIdx.x, b = blockIdx.y;
    int tid = threadIdx.x;

    for (int idx = tid; idx < OUTo * Cc; idx += 256) {
        int o = idx >> 6, c = idx & 63;
        w3t[c * OUTo + o] = W3[idx];
    }
    const float4* zg4 = reinterpret_cast<const float4*>(
        g_z + (size_t)b * (Cc * Tt * Vv) + nt * 128);
    float4* zs4 = reinterpret_cast<float4*>(zs);
    for (int f = tid; f < Cc * 32; f += 256) {
        int c = f >> 5, j = f & 31;
        zs4[c * 32 + j] = zg4[(size_t)c * 800 + j];
    }
    __syncthreads();

    int w = tid >> 5, lane = tid & 31;
    int o0 = w * 8, n0 = lane * 4;

    ull acc[4][4];     // [o-pair][n]
    #pragma unroll
    for (int p = 0; p < 4; p++)
        #pragma unroll
        for (int q = 0; q < 4; q++) acc[p][q] = 0ull;

    #pragma unroll 4
    for (int c = 0; c < Cc; c++) {
        const ulonglong2* wp =
            reinterpret_cast<const ulonglong2*>(&w3t[c * OUTo + o0]);
        ulonglong2 wa = wp[0];   // warp-uniform broadcast
        ulonglong2 wb = wp[1];
        float4 z4 = *reinterpret_cast<const float4*>(&zs[c * 128 + n0]);
        ull zs0 = splat2(z4.x), zs1 = splat2(z4.y);
        ull zs2 = splat2(z4.z), zs3 = splat2(z4.w);
        ffma2(acc[0][0], wa.x, zs0); ffma2(acc[0][1], wa.x, zs1);
        ffma2(acc[0][2], wa.x, zs2); ffma2(acc[0][3], wa.x, zs3);
        ffma2(acc[1][0], wa.y, zs0); ffma2(acc[1][1], wa.y, zs1);
        ffma2(acc[1][2], wa.y, zs2); ffma2(acc[1][3], wa.y, zs3);
        ffma2(acc[2][0], wb.x, zs0); ffma2(acc[2][1], wb.x, zs1);
        ffma2(acc[2][2], wb.x, zs2); ffma2(acc[2][3], wb.x, zs3);
        ffma2(acc[3][0], wb.y, zs0); ffma2(acc[3][1], wb.y, zs1);
        ffma2(acc[3][2], wb.y, zs2); ffma2(acc[3][3], wb.y, zs3);
    }

    float* ob = out + (size_t)b * OUTo * (Tt * Vv) + nt * 128 + n0;
    #pragma unroll
    for (int p = 0; p < 4; p++) {
        int oA = o0 + 2 * p, oB = oA + 1;
        float bA = __ldg(&b3[oA]), bB = __ldg(&b3[oB]);
        float2 f0 = lo_hi(acc[p][0]), f1 = lo_hi(acc[p][1]);
        float2 f2 = lo_hi(acc[p][2]), f3 = lo_hi(acc[p][3]);
        float4 vA = make_float4(f0.x + bA, f1.x + bA, f2.x + bA, f3.x + bA);
        float4 vB = make_float4(f0.y + bB, f1.y + bB, f2.y + bB, f3.y + bB);
        *reinterpret_cast<float4*>(ob + (size_t)oA * (Tt * Vv)) = vA;
        *reinterpret_cast<float4*>(ob + (size_t)oB * (Tt * Vv)) = vB;
    }
}

// ============================================================
extern "C" void kernel_launch(void* const* d_in, const int* in_sizes, int n_in,
                              void* d_out, int out_size) {
    const float* x  = (const float*)d_in[0];
    const float* A  = (const float*)d_in[1];
    const float* W1 = (const float*)d_in[2];
    const float* b1 = (const float*)d_in[3];
    const float* W2 = (const float*)d_in[4];
    const float* b2 = (const float*)d_in[5];
    const float* W4 = (const float*)d_in[6];
    const float* b4 = (const float*)d_in[7];
    const float* W3 = (const float*)d_in[8];
    const float* b3 = (const float*)d_in[9];
    float* out = (float*)d_out;

    k1_xbar<<<Bb * Cc, 128>>>(x);
    k2_rel<<<Bb, 256>>>(W1, b1, W2, b2);
    k3_z<<<Bb * Cc, 128>>>(x, A, W4, b4);
    k4_conv3<<<dim3(25, Bb), 256>>>(W3, b3, out);
}